// round 7
// baseline (speedup 1.0000x reference)
#include <cuda_runtime.h>
#include <cstdint>

// ---------------------------------------------------------------------------
// Fused SelfAttention (attention over heads axis):
//   qkv = v @ {Wq,Wk,Wv}   (tf32 mma, fp32 accum)
//   per token: attn = softmax((q_h . k_g)/sqrt(32)) over g (8x8), x = attn @ vv
//   out = x @ Wp + bp      (tf32 mma, fp32 accum)
// One CTA = 32 tokens. R6: vectorized STS.128 staging (kills 4-way bank
// conflicts), double-buffered KC=32 weight chunks with register prefetch
// (hides L2 latency behind MMA), vectorized LDS.128 phase-2 reads.
// ---------------------------------------------------------------------------

#define NUM_H   8
#define HD      32
#define DIM     256
#define BT      32      // tokens per CTA
#define NTH     256     // threads per CTA (8 warps)
#define KC      32      // K-chunk rows per weight buffer (double-buffered)

// SMEM strides (in 4-byte words):
//  STR_VX % 32 == 4  -> A-frag lanes (g*4 + tig) hit distinct banks
//  STR_W  % 32 == 8  -> B-frag lanes (tig*8 + g) hit distinct banks
//  STR_Q  % 32 == 4  -> phase-2 LDS.128 per-lane-token reads conflict-free
#define STR_VX  260
#define STR_W   264
#define STR_Q   772

#define OFF_VX  0
#define OFF_W   (BT * STR_VX * 4)            // 33280
#define WBUF_W  (KC * STR_W)                 // words per weight buffer (8448)
#define OFF_Q   (OFF_W + 2 * WBUF_W * 4)     // 33280 + 67584 = 100864
#define SMEM_BYTES (OFF_Q + BT * STR_Q * 4)  // + 98816 = 199680 bytes

__device__ __forceinline__ uint32_t f2tf(float f) {
    uint32_t u;
    asm("cvt.rna.tf32.f32 %0, %1;" : "=r"(u) : "f"(f));
    return u;
}

__device__ __forceinline__ void mma_tf32(float d[4], const uint32_t a[4], const uint32_t b[2]) {
    asm volatile(
        "mma.sync.aligned.m16n8k8.row.col.f32.tf32.tf32.f32 "
        "{%0,%1,%2,%3}, {%4,%5,%6,%7}, {%8,%9}, {%0,%1,%2,%3};"
        : "+f"(d[0]), "+f"(d[1]), "+f"(d[2]), "+f"(d[3])
        : "r"(a[0]), "r"(a[1]), "r"(a[2]), "r"(a[3]), "r"(b[0]), "r"(b[1]));
}

// Load one [KC x 256] fp32 weight chunk into registers (coalesced LDG.128).
__device__ __forceinline__ void ldg_chunk(float4 pre[8], const float4* __restrict__ W4,
                                          int kc, int tid) {
    const float4* src = W4 + (size_t)kc * (KC * DIM / 4);
    #pragma unroll
    for (int i = 0; i < 8; ++i) pre[i] = src[tid + NTH * i];
}

// Convert registers to tf32 and store into a weight buffer (clean STS.128:
// each warp covers a contiguous 512B half-row).
__device__ __forceinline__ void cvt_sts(uint32_t* __restrict__ buf,
                                        const float4 pre[8], int tid) {
    #pragma unroll
    for (int i = 0; i < 8; ++i) {
        int f  = tid + NTH * i;
        int r  = f >> 6;          // row within chunk (64 float4 per row)
        int c4 = f & 63;
        uint4 u = make_uint4(f2tf(pre[i].x), f2tf(pre[i].y),
                             f2tf(pre[i].z), f2tf(pre[i].w));
        *reinterpret_cast<uint4*>(buf + r * STR_W + c4 * 4) = u;
    }
}

// KC/8 k-steps of m16n8k8 tf32 mma from one weight buffer.
// acc[mi][j][4]: mi = m-frag (rows mi*16..+15), j = n-frag (cols nb+j*8..+7).
__device__ __forceinline__ void mma_chunk(float acc[2][4][4],
                                          const uint32_t* __restrict__ sA,
                                          const uint32_t* __restrict__ sW,
                                          int g, int tig, int nb, int kbase) {
    #pragma unroll
    for (int k8 = 0; k8 < KC / 8; ++k8) {
        int kk = k8 * 8;
        uint32_t a[2][4];
        #pragma unroll
        for (int mi = 0; mi < 2; ++mi) {
            int r = mi * 16 + g;
            int c = kbase + kk + tig;         // global K column in sVX
            a[mi][0] = sA[r * STR_VX + c];
            a[mi][1] = sA[(r + 8) * STR_VX + c];
            a[mi][2] = sA[r * STR_VX + c + 4];
            a[mi][3] = sA[(r + 8) * STR_VX + c + 4];
        }
        #pragma unroll
        for (int j = 0; j < 4; ++j) {
            int n = nb + j * 8 + g;
            uint32_t b[2];
            b[0] = sW[(kk + tig) * STR_W + n];
            b[1] = sW[(kk + tig + 4) * STR_W + n];
            mma_tf32(acc[0][j], a[0], b);
            mma_tf32(acc[1][j], a[1], b);
        }
    }
}

// One full 32x256x256 GEMM: 8 chunks of KC=32, double-buffered, register
// prefetch pipeline (LDG next -> MMA current -> STS next -> sync).
__device__ __forceinline__ void gemm(float acc[2][4][4], const float* __restrict__ Wsel,
                                     const uint32_t* __restrict__ sVX,
                                     uint32_t* __restrict__ sWbase,
                                     int tid, int g, int tig, int nb) {
    const float4* W4 = reinterpret_cast<const float4*>(Wsel);
    float4 pre[8];
    ldg_chunk(pre, W4, 0, tid);
    cvt_sts(sWbase, pre, tid);
    __syncthreads();
    #pragma unroll 1
    for (int kc = 0; kc < DIM / KC; ++kc) {
        uint32_t* cur = sWbase + (kc & 1) * WBUF_W;
        if (kc < DIM / KC - 1) ldg_chunk(pre, W4, kc + 1, tid);   // prefetch
        mma_chunk(acc, sVX, cur, g, tig, nb, kc * KC);
        if (kc < DIM / KC - 1) {
            cvt_sts(sWbase + ((kc + 1) & 1) * WBUF_W, pre, tid);
            __syncthreads();
        }
    }
}

__global__ void __launch_bounds__(NTH)
SelfAttention_695784702010_kernel(const float* __restrict__ v,
                                  const float* __restrict__ Wq,
                                  const float* __restrict__ Wk,
                                  const float* __restrict__ Wv,
                                  const float* __restrict__ Wp,
                                  const float* __restrict__ bp,
                                  float* __restrict__ out) {
    extern __shared__ char smem[];
    uint32_t* sVX  = reinterpret_cast<uint32_t*>(smem + OFF_VX);  // v tile (tf32), later x tile
    uint32_t* sW   = reinterpret_cast<uint32_t*>(smem + OFF_W);   // 2x weight chunk buffers
    float*    sQKV = reinterpret_cast<float*>(smem + OFF_Q);      // [32][768] fp32 q|k|vv

    const int tid  = threadIdx.x;
    const int wid  = tid >> 5;
    const int lane = tid & 31;
    const int g    = lane >> 2;   // groupID
    const int tig  = lane & 3;    // thread-in-group

    const size_t rowBase = (size_t)blockIdx.x * BT;
    const float* vBlk = v + rowBase * DIM;

    // ---- Stage v tile [32 x 256] -> tf32 (vectorized, conflict-free) ------
    {
        const float4* src = reinterpret_cast<const float4*>(vBlk);
        #pragma unroll
        for (int i = 0; i < (BT * DIM / 4) / NTH; ++i) {   // 8 float4 per thread
            int f  = tid + i * NTH;
            int r  = f >> 6;
            int c4 = f & 63;
            float4 x = src[f];
            uint4 u = make_uint4(f2tf(x.x), f2tf(x.y), f2tf(x.z), f2tf(x.w));
            *reinterpret_cast<uint4*>(sVX + r * STR_VX + c4 * 4) = u;
        }
    }
    __syncthreads();

    // ---- Phase 1: qkv = v @ {Wq, Wk, Wv} ---------------------------------
    #pragma unroll 1
    for (int nc = 0; nc < 3; ++nc) {
        const float* Wsel = (nc == 0) ? Wq : (nc == 1) ? Wk : Wv;
        float acc[2][4][4] = {};
        gemm(acc, Wsel, sVX, sW, tid, g, tig, wid * 32);
        // Fragment layout: d0:(g,2t) d1:(g,2t+1) d2:(g+8,2t) d3:(g+8,2t+1)
        #pragma unroll
        for (int mi = 0; mi < 2; ++mi) {
            #pragma unroll
            for (int j = 0; j < 4; ++j) {
                int row = mi * 16 + g;
                int col = nc * 256 + wid * 32 + j * 8 + 2 * tig;
                *reinterpret_cast<float2*>(sQKV + row * STR_Q + col) =
                    make_float2(acc[mi][j][0], acc[mi][j][1]);
                *reinterpret_cast<float2*>(sQKV + (row + 8) * STR_Q + col) =
                    make_float2(acc[mi][j][2], acc[mi][j][3]);
            }
        }
    }
    __syncthreads();

    // ---- Phase 2: per-token 8x8 heads-attention (vectorized LDS.128) ------
    // thread = (head h = wid, token t = lane); softmax over g for fixed h.
    {
        const int h = wid, t = lane;
        const float4* qp4 = reinterpret_cast<const float4*>(sQKV + t * STR_Q + h * HD);
        const float4* kp4 = reinterpret_cast<const float4*>(sQKV + t * STR_Q + 256);
        const float4* vp4 = reinterpret_cast<const float4*>(sQKV + t * STR_Q + 512);

        float4 q[HD / 4];
        #pragma unroll
        for (int i = 0; i < HD / 4; ++i) q[i] = qp4[i];

        float a[NUM_H];
        float mx = -1e30f;
        #pragma unroll
        for (int gg = 0; gg < NUM_H; ++gg) {
            float s = 0.f;
            #pragma unroll
            for (int i = 0; i < HD / 4; ++i) {
                float4 kv = kp4[gg * (HD / 4) + i];
                s += q[i].x * kv.x + q[i].y * kv.y + q[i].z * kv.z + q[i].w * kv.w;
            }
            s *= 0.17677669529663687f;   // 1/sqrt(32)
            a[gg] = s;
            mx = fmaxf(mx, s);
        }
        float sum = 0.f;
        #pragma unroll
        for (int gg = 0; gg < NUM_H; ++gg) { a[gg] = __expf(a[gg] - mx); sum += a[gg]; }
        float inv = 1.f / sum;
        #pragma unroll
        for (int gg = 0; gg < NUM_H; ++gg) a[gg] *= inv;

        uint32_t* xp = sVX + t * STR_VX + h * HD;   // reuse v-tile region for x (tf32)
        #pragma unroll
        for (int i = 0; i < HD / 4; ++i) {
            float4 s = make_float4(0.f, 0.f, 0.f, 0.f);
            #pragma unroll
            for (int gg = 0; gg < NUM_H; ++gg) {
                float4 vv = vp4[gg * (HD / 4) + i];
                s.x += a[gg] * vv.x; s.y += a[gg] * vv.y;
                s.z += a[gg] * vv.z; s.w += a[gg] * vv.w;
            }
            uint4 u = make_uint4(f2tf(s.x), f2tf(s.y), f2tf(s.z), f2tf(s.w));
            *reinterpret_cast<uint4*>(xp + i * 4) = u;
        }
    }
    __syncthreads();

    // ---- Phase 3: out = x @ Wp + bp --------------------------------------
    {
        float acc[2][4][4] = {};
        float bias[4][2];
        #pragma unroll
        for (int j = 0; j < 4; ++j) {
            int n = wid * 32 + j * 8 + 2 * tig;
            bias[j][0] = bp[n];
            bias[j][1] = bp[n + 1];
        }
        gemm(acc, Wp, sVX, sW, tid, g, tig, wid * 32);

        float* outBlk = out + rowBase * DIM;
        #pragma unroll
        for (int mi = 0; mi < 2; ++mi) {
            #pragma unroll
            for (int j = 0; j < 4; ++j) {
                int row = mi * 16 + g;
                int n = wid * 32 + j * 8 + 2 * tig;
                float2 lo = make_float2(acc[mi][j][0] + bias[j][0],
                                        acc[mi][j][1] + bias[j][1]);
                float2 hi = make_float2(acc[mi][j][2] + bias[j][0],
                                        acc[mi][j][3] + bias[j][1]);
                *reinterpret_cast<float2*>(outBlk + (size_t)row * DIM + n)       = lo;
                *reinterpret_cast<float2*>(outBlk + (size_t)(row + 8) * DIM + n) = hi;
            }
        }
    }
}

extern "C" void kernel_launch(void* const* d_in, const int* in_sizes, int n_in,
                              void* d_out, int out_size) {
    const float* v  = (const float*)d_in[0];
    const float* Wq = (const float*)d_in[1];
    const float* Wk = (const float*)d_in[2];
    const float* Wv = (const float*)d_in[3];
    const float* Wp = (const float*)d_in[4];
    const float* bp = (const float*)d_in[5];
    float* out = (float*)d_out;

    cudaFuncSetAttribute(SelfAttention_695784702010_kernel,
                         cudaFuncAttributeMaxDynamicSharedMemorySize, SMEM_BYTES);

    int M = in_sizes[0] / DIM;          // 65536 tokens
    int grid = M / BT;                  // 2048 CTAs
    SelfAttention_695784702010_kernel<<<grid, NTH, SMEM_BYTES>>>(v, Wq, Wk, Wv, Wp, bp, out);
}

// round 9
// speedup vs baseline: 1.1691x; 1.1691x over previous
#include <cuda_runtime.h>
#include <cstdint>

// ---------------------------------------------------------------------------
// Fused SelfAttention (attention over heads axis), split into two kernels to
// double occupancy (R8):
//   K1: qkv = v @ {Wq,Wk,Wv}  -> __device__ scratch (transposed per block)
//   K2: per-token 8x8 heads softmax-attention + out = x @ Wp + bp
// Each kernel uses ~101 KB smem -> 2 CTAs/SM (16 warps) instead of 1 (8).
// ---------------------------------------------------------------------------

#define NUM_H   8
#define HD      32
#define DIM     256
#define BT      32      // tokens per CTA
#define NTH     256     // threads per CTA (8 warps)
#define KC      32      // K-chunk rows per weight buffer (double-buffered)

// SMEM strides (in 4-byte words):
//  STR_VX % 32 == 4  -> A-frag lanes (g*4 + tig) hit distinct banks
//  STR_W  % 32 == 8  -> B-frag lanes (tig*8 + g) hit distinct banks
#define STR_VX  260
#define STR_W   264

#define OFF_VX  0
#define OFF_W   (BT * STR_VX * 4)            // 33280
#define WBUF_W  (KC * STR_W)                 // words per weight buffer (8448)
#define SMEM_BYTES (OFF_W + 2 * WBUF_W * 4)  // 33280 + 67584 = 100864 bytes

// qkv scratch: per 32-token block, 3 sections (q|k|vv), each [256 cols][32 tok]
#define SEC_W    (DIM * BT)                  // 8192 words per section
#define BLK_W    (3 * SEC_W)                 // 24576 words per block
#define NBLK     2048
__device__ float g_qkv[(size_t)NBLK * BLK_W];   // 192 MiB static scratch

__device__ __forceinline__ uint32_t f2tf(float f) {
    uint32_t u;
    asm("cvt.rna.tf32.f32 %0, %1;" : "=r"(u) : "f"(f));
    return u;
}

__device__ __forceinline__ void mma_tf32(float d[4], const uint32_t a[4], const uint32_t b[2]) {
    asm volatile(
        "mma.sync.aligned.m16n8k8.row.col.f32.tf32.tf32.f32 "
        "{%0,%1,%2,%3}, {%4,%5,%6,%7}, {%8,%9}, {%0,%1,%2,%3};"
        : "+f"(d[0]), "+f"(d[1]), "+f"(d[2]), "+f"(d[3])
        : "r"(a[0]), "r"(a[1]), "r"(a[2]), "r"(a[3]), "r"(b[0]), "r"(b[1]));
}

// Load one [KC x 256] fp32 weight chunk into registers (coalesced LDG.128).
__device__ __forceinline__ void ldg_chunk(float4 pre[8], const float4* __restrict__ W4,
                                          int kc, int tid) {
    const float4* src = W4 + (size_t)kc * (KC * DIM / 4);
    #pragma unroll
    for (int i = 0; i < 8; ++i) pre[i] = src[tid + NTH * i];
}

// Convert registers to tf32 and store into a weight buffer (STS.128,
// each warp covers a contiguous 512B half-row -> conflict-free).
__device__ __forceinline__ void cvt_sts(uint32_t* __restrict__ buf,
                                        const float4 pre[8], int tid) {
    #pragma unroll
    for (int i = 0; i < 8; ++i) {
        int f  = tid + NTH * i;
        int r  = f >> 6;
        int c4 = f & 63;
        uint4 u = make_uint4(f2tf(pre[i].x), f2tf(pre[i].y),
                             f2tf(pre[i].z), f2tf(pre[i].w));
        *reinterpret_cast<uint4*>(buf + r * STR_W + c4 * 4) = u;
    }
}

// KC/8 k-steps of m16n8k8 tf32 mma from one weight buffer.
__device__ __forceinline__ void mma_chunk(float acc[2][4][4],
                                          const uint32_t* __restrict__ sA,
                                          const uint32_t* __restrict__ sW,
                                          int g, int tig, int nb, int kbase) {
    #pragma unroll
    for (int k8 = 0; k8 < KC / 8; ++k8) {
        int kk = k8 * 8;
        uint32_t a[2][4];
        #pragma unroll
        for (int mi = 0; mi < 2; ++mi) {
            int r = mi * 16 + g;
            int c = kbase + kk + tig;
            a[mi][0] = sA[r * STR_VX + c];
            a[mi][1] = sA[(r + 8) * STR_VX + c];
            a[mi][2] = sA[r * STR_VX + c + 4];
            a[mi][3] = sA[(r + 8) * STR_VX + c + 4];
        }
        #pragma unroll
        for (int j = 0; j < 4; ++j) {
            int n = nb + j * 8 + g;
            uint32_t b[2];
            b[0] = sW[(kk + tig) * STR_W + n];
            b[1] = sW[(kk + tig + 4) * STR_W + n];
            mma_tf32(acc[0][j], a[0], b);
            mma_tf32(acc[1][j], a[1], b);
        }
    }
}

// One 32x256x256 GEMM: 8 chunks of KC=32, double-buffered, register prefetch.
__device__ __forceinline__ void gemm(float acc[2][4][4], const float* __restrict__ Wsel,
                                     const uint32_t* __restrict__ sVX,
                                     uint32_t* __restrict__ sWbase,
                                     int tid, int g, int tig, int nb) {
    const float4* W4 = reinterpret_cast<const float4*>(Wsel);
    float4 pre[8];
    ldg_chunk(pre, W4, 0, tid);
    cvt_sts(sWbase, pre, tid);
    __syncthreads();
    #pragma unroll 1
    for (int kc = 0; kc < DIM / KC; ++kc) {
        uint32_t* cur = sWbase + (kc & 1) * WBUF_W;
        if (kc < DIM / KC - 1) ldg_chunk(pre, W4, kc + 1, tid);   // prefetch
        mma_chunk(acc, sVX, cur, g, tig, nb, kc * KC);
        if (kc < DIM / KC - 1) {
            cvt_sts(sWbase + ((kc + 1) & 1) * WBUF_W, pre, tid);
            __syncthreads();
        }
    }
}

// ========================= Kernel 1: qkv projections ========================
__global__ void __launch_bounds__(NTH, 2)
sa_qkv_kernel(const float* __restrict__ v,
              const float* __restrict__ Wq,
              const float* __restrict__ Wk,
              const float* __restrict__ Wv) {
    extern __shared__ char smem[];
    uint32_t* sVX = reinterpret_cast<uint32_t*>(smem + OFF_VX);
    uint32_t* sW  = reinterpret_cast<uint32_t*>(smem + OFF_W);

    const int tid  = threadIdx.x;
    const int wid  = tid >> 5;
    const int lane = tid & 31;
    const int g    = lane >> 2;
    const int tig  = lane & 3;

    const size_t rowBase = (size_t)blockIdx.x * BT;
    const float* vBlk = v + rowBase * DIM;

    // Stage v tile [32 x 256] -> tf32
    {
        const float4* src = reinterpret_cast<const float4*>(vBlk);
        #pragma unroll
        for (int i = 0; i < (BT * DIM / 4) / NTH; ++i) {
            int f  = tid + i * NTH;
            int r  = f >> 6;
            int c4 = f & 63;
            float4 x = src[f];
            uint4 u = make_uint4(f2tf(x.x), f2tf(x.y), f2tf(x.z), f2tf(x.w));
            *reinterpret_cast<uint4*>(sVX + r * STR_VX + c4 * 4) = u;
        }
    }
    __syncthreads();

    float* blkScr = g_qkv + (size_t)blockIdx.x * BLK_W;
    #pragma unroll 1
    for (int nc = 0; nc < 3; ++nc) {
        const float* Wsel = (nc == 0) ? Wq : (nc == 1) ? Wk : Wv;
        float acc[2][4][4] = {};
        gemm(acc, Wsel, sVX, sW, tid, g, tig, wid * 32);
        // Write fragments transposed: scratch[sec][col][token]
        float* dst = blkScr + nc * SEC_W;
        #pragma unroll
        for (int mi = 0; mi < 2; ++mi) {
            #pragma unroll
            for (int j = 0; j < 4; ++j) {
                int col = wid * 32 + j * 8 + 2 * tig;
                int r0 = mi * 16 + g, r1 = r0 + 8;
                dst[col * BT + r0]       = acc[mi][j][0];
                dst[(col + 1) * BT + r0] = acc[mi][j][1];
                dst[col * BT + r1]       = acc[mi][j][2];
                dst[(col + 1) * BT + r1] = acc[mi][j][3];
            }
        }
    }
}

// ================= Kernel 2: heads-attention + output proj ==================
__global__ void __launch_bounds__(NTH, 2)
sa_attn_out_kernel(const float* __restrict__ Wp,
                   const float* __restrict__ bp,
                   float* __restrict__ out) {
    extern __shared__ char smem[];
    uint32_t* sVX = reinterpret_cast<uint32_t*>(smem + OFF_VX);   // x tile (tf32)
    uint32_t* sW  = reinterpret_cast<uint32_t*>(smem + OFF_W);

    const int tid  = threadIdx.x;
    const int wid  = tid >> 5;
    const int lane = tid & 31;
    const int g    = lane >> 2;
    const int tig  = lane & 3;

    const float* blkScr = g_qkv + (size_t)blockIdx.x * BLK_W;

    // ---- Per-token 8x8 heads-attention: thread = (head h=wid, token t=lane)
    // Scratch is [col][token], so lane==token -> all loads coalesced.
    {
        const int h = wid, t = lane;
        const float* qp = blkScr + (h * HD) * BT + t;       // q, this head's cols
        const float* kp = blkScr + SEC_W + t;               // k, all cols
        const float* vp = blkScr + 2 * SEC_W + t;           // vv, all cols

        float q[HD];
        #pragma unroll
        for (int d = 0; d < HD; ++d) q[d] = qp[d * BT];

        float a[NUM_H];
        float mx = -1e30f;
        #pragma unroll
        for (int gg = 0; gg < NUM_H; ++gg) {
            float s = 0.f;
            #pragma unroll
            for (int d = 0; d < HD; ++d) s += q[d] * kp[(gg * HD + d) * BT];
            s *= 0.17677669529663687f;   // 1/sqrt(32)
            a[gg] = s;
            mx = fmaxf(mx, s);
        }
        float sum = 0.f;
        #pragma unroll
        for (int gg = 0; gg < NUM_H; ++gg) { a[gg] = __expf(a[gg] - mx); sum += a[gg]; }
        float inv = 1.f / sum;
        #pragma unroll
        for (int gg = 0; gg < NUM_H; ++gg) a[gg] *= inv;

        uint32_t* xp = sVX + t * STR_VX + h * HD;
        #pragma unroll
        for (int d = 0; d < HD; ++d) {
            float s = 0.f;
            #pragma unroll
            for (int gg = 0; gg < NUM_H; ++gg) s += a[gg] * vp[(gg * HD + d) * BT];
            xp[d] = f2tf(s);
        }
    }
    __syncthreads();

    // ---- out = x @ Wp + bp
    {
        float acc[2][4][4] = {};
        float bias[4][2];
        #pragma unroll
        for (int j = 0; j < 4; ++j) {
            int n = wid * 32 + j * 8 + 2 * tig;
            bias[j][0] = bp[n];
            bias[j][1] = bp[n + 1];
        }
        gemm(acc, Wp, sVX, sW, tid, g, tig, wid * 32);

        float* outBlk = out + (size_t)blockIdx.x * BT * DIM;
        #pragma unroll
        for (int mi = 0; mi < 2; ++mi) {
            #pragma unroll
            for (int j = 0; j < 4; ++j) {
                int row = mi * 16 + g;
                int n = wid * 32 + j * 8 + 2 * tig;
                float2 lo = make_float2(acc[mi][j][0] + bias[j][0],
                                        acc[mi][j][1] + bias[j][1]);
                float2 hi = make_float2(acc[mi][j][2] + bias[j][0],
                                        acc[mi][j][3] + bias[j][1]);
                *reinterpret_cast<float2*>(outBlk + (size_t)row * DIM + n)       = lo;
                *reinterpret_cast<float2*>(outBlk + (size_t)(row + 8) * DIM + n) = hi;
            }
        }
    }
}

extern "C" void kernel_launch(void* const* d_in, const int* in_sizes, int n_in,
                              void* d_out, int out_size) {
    const float* v  = (const float*)d_in[0];
    const float* Wq = (const float*)d_in[1];
    const float* Wk = (const float*)d_in[2];
    const float* Wv = (const float*)d_in[3];
    const float* Wp = (const float*)d_in[4];
    const float* bp = (const float*)d_in[5];
    float* out = (float*)d_out;

    cudaFuncSetAttribute(sa_qkv_kernel,
                         cudaFuncAttributeMaxDynamicSharedMemorySize, SMEM_BYTES);
    cudaFuncSetAttribute(sa_attn_out_kernel,
                         cudaFuncAttributeMaxDynamicSharedMemorySize, SMEM_BYTES);

    int M = in_sizes[0] / DIM;          // 65536 tokens
    int grid = M / BT;                  // 2048 CTAs
    sa_qkv_kernel<<<grid, NTH, SMEM_BYTES>>>(v, Wq, Wk, Wv);
    sa_attn_out_kernel<<<grid, NTH, SMEM_BYTES>>>(Wp, bp, out);
}

// round 10
// speedup vs baseline: 1.5743x; 1.3465x over previous
#include <cuda_runtime.h>
#include <cstdint>

// ---------------------------------------------------------------------------
// Fused SelfAttention (attention over heads axis), 3 kernels (R10):
//   K0: weights fp32 -> tf32 once (removes cvt from hot loop)
//   K1: qkv = v @ {Wq,Wk,Wv} -> scratch (transposed per 64-token block)
//   K2: per-token 8x8 heads softmax-attention + out = x @ Wp + bp
// BT=64 tokens/CTA halves per-token weight staging; weight chunks staged via
// cp.async (no registers, no cvt, no STS); double-buffered KC=16 chunks.
// ---------------------------------------------------------------------------

#define NUM_H   8
#define HD      32
#define DIM     256
#define BT      64      // tokens per CTA
#define NTH     256     // threads per CTA (8 warps)
#define KC      16      // K-chunk rows per weight buffer (double-buffered)
#define NCHUNK  (DIM / KC)   // 16

// SMEM strides (words): STR_VX%32==4 (A-frags conflict-free),
// STR_W%32==8 (B-frags conflict-free, cp.async rows contiguous 16B-wise)
#define STR_VX  260
#define STR_W   264

#define OFF_VX  0
#define OFF_W   (BT * STR_VX * 4)            // 66560
#define WBUF_W  (KC * STR_W)                 // 4224 words per buffer
#define WBUF_B  (WBUF_W * 4)                 // 16896 bytes
#define SMEM_BYTES (OFF_W + 2 * WBUF_B)      // 100352 bytes -> 2 CTAs/SM

// qkv scratch: per 64-token block, 3 sections (q|k|vv), each [256 cols][64 tok]
#define SEC_W    (DIM * BT)                  // 16384 words
#define BLK_W    (3 * SEC_W)                 // 49152 words
#define NBLK     1024
__device__ float    g_qkv[(size_t)NBLK * BLK_W];   // 192 MiB scratch
__device__ uint32_t g_wtf[4 * DIM * DIM];          // tf32 weights: q,k,v,p

__device__ __forceinline__ uint32_t f2tf(float f) {
    uint32_t u;
    asm("cvt.rna.tf32.f32 %0, %1;" : "=r"(u) : "f"(f));
    return u;
}

__device__ __forceinline__ void mma_tf32(float d[4], const uint32_t a[4], const uint32_t b[2]) {
    asm volatile(
        "mma.sync.aligned.m16n8k8.row.col.f32.tf32.tf32.f32 "
        "{%0,%1,%2,%3}, {%4,%5,%6,%7}, {%8,%9}, {%0,%1,%2,%3};"
        : "+f"(d[0]), "+f"(d[1]), "+f"(d[2]), "+f"(d[3])
        : "r"(a[0]), "r"(a[1]), "r"(a[2]), "r"(a[3]), "r"(b[0]), "r"(b[1]));
}

__device__ __forceinline__ void cp16(uint32_t dst, const void* src) {
    asm volatile("cp.async.cg.shared.global [%0], [%1], 16;" :: "r"(dst), "l"(src));
}
#define CP_COMMIT()  asm volatile("cp.async.commit_group;")
#define CP_WAIT(n)   asm volatile("cp.async.wait_group %0;" :: "n"(n))

// Issue cp.async for one [KC x 256] tf32 weight chunk into a smem buffer.
// 1024 x 16B per chunk / 256 threads = 4 per thread; each warp covers a
// contiguous half-row -> conflict-free.
__device__ __forceinline__ void issue_chunk(uint32_t swByte, const uint32_t* __restrict__ Wtf,
                                            int kc, int tid) {
    const uint32_t* src = Wtf + (size_t)kc * KC * DIM;
    #pragma unroll
    for (int i = 0; i < 4; ++i) {
        int f  = tid + NTH * i;       // float4 index within chunk
        int r  = f >> 6;
        int c4 = f & 63;
        cp16(swByte + (uint32_t)(r * STR_W + c4 * 4) * 4, src + f * 4);
    }
}

// KC/8 k-steps of m16n8k8 for a 64-row tile (4 m-frags) x 32 cols (4 n-frags).
__device__ __forceinline__ void mma_chunk(float acc[4][4][4],
                                          const uint32_t* __restrict__ sA,
                                          const uint32_t* __restrict__ sW,
                                          int g, int tig, int nb, int kbase) {
    #pragma unroll
    for (int k8 = 0; k8 < KC / 8; ++k8) {
        int kk = k8 * 8;
        uint32_t a[4][4];
        #pragma unroll
        for (int mf = 0; mf < 4; ++mf) {
            int r = mf * 16 + g;
            int c = kbase + kk + tig;
            a[mf][0] = sA[r * STR_VX + c];
            a[mf][1] = sA[(r + 8) * STR_VX + c];
            a[mf][2] = sA[r * STR_VX + c + 4];
            a[mf][3] = sA[(r + 8) * STR_VX + c + 4];
        }
        #pragma unroll
        for (int j = 0; j < 4; ++j) {
            int n = nb + j * 8 + g;
            uint32_t b[2];
            b[0] = sW[(kk + tig) * STR_W + n];
            b[1] = sW[(kk + tig + 4) * STR_W + n];
            #pragma unroll
            for (int mf = 0; mf < 4; ++mf) mma_tf32(acc[mf][j], a[mf], b);
        }
    }
}

// 64x256x256 GEMM: 16 chunks of KC=16, cp.async double-buffered.
__device__ __forceinline__ void gemm64(float acc[4][4][4], const uint32_t* __restrict__ Wtf,
                                       const uint32_t* __restrict__ sVX,
                                       const uint32_t* __restrict__ sW,
                                       uint32_t swByte,
                                       int tid, int g, int tig, int nb) {
    issue_chunk(swByte, Wtf, 0, tid);           CP_COMMIT();
    issue_chunk(swByte + WBUF_B, Wtf, 1, tid);  CP_COMMIT();
    #pragma unroll 1
    for (int kc = 0; kc < NCHUNK; ++kc) {
        if (kc < NCHUNK - 1) { CP_WAIT(1); } else { CP_WAIT(0); }
        __syncthreads();                         // chunk kc visible to all
        mma_chunk(acc, sVX, sW + (kc & 1) * WBUF_W, g, tig, nb, kc * KC);
        __syncthreads();                         // buf (kc&1) fully consumed
        if (kc + 2 < NCHUNK) {
            issue_chunk(swByte + (kc & 1) * WBUF_B, Wtf, kc + 2, tid);
            CP_COMMIT();
        }
    }
}

// ==================== K0: convert weights fp32 -> tf32 ======================
__global__ void __launch_bounds__(NTH)
cvt_weights_kernel(const float* __restrict__ Wq, const float* __restrict__ Wk,
                   const float* __restrict__ Wv, const float* __restrict__ Wp) {
    int f = blockIdx.x * NTH + threadIdx.x;      // float4 index, 16384/matrix
    const float* srcs[4] = {Wq, Wk, Wv, Wp};
    uint4* dst = reinterpret_cast<uint4*>(g_wtf);
    #pragma unroll
    for (int m = 0; m < 4; ++m) {
        float4 x = reinterpret_cast<const float4*>(srcs[m])[f];
        dst[m * (DIM * DIM / 4) + f] =
            make_uint4(f2tf(x.x), f2tf(x.y), f2tf(x.z), f2tf(x.w));
    }
}

// ========================= K1: qkv projections ==============================
__global__ void __launch_bounds__(NTH, 2)
sa_qkv_kernel(const float* __restrict__ v) {
    extern __shared__ char smem[];
    uint32_t* sVX = reinterpret_cast<uint32_t*>(smem + OFF_VX);
    uint32_t* sW  = reinterpret_cast<uint32_t*>(smem + OFF_W);
    uint32_t swByte = (uint32_t)__cvta_generic_to_shared(smem + OFF_W);

    const int tid  = threadIdx.x;
    const int wid  = tid >> 5;
    const int lane = tid & 31;
    const int g    = lane >> 2;
    const int tig  = lane & 3;

    // Stage v tile [64 x 256] -> tf32
    {
        const float4* src = reinterpret_cast<const float4*>(v + (size_t)blockIdx.x * BT * DIM);
        #pragma unroll
        for (int i = 0; i < (BT * DIM / 4) / NTH; ++i) {   // 16 per thread
            int f  = tid + i * NTH;
            int r  = f >> 6;
            int c4 = f & 63;
            float4 x = src[f];
            uint4 u = make_uint4(f2tf(x.x), f2tf(x.y), f2tf(x.z), f2tf(x.w));
            *reinterpret_cast<uint4*>(sVX + r * STR_VX + c4 * 4) = u;
        }
    }
    __syncthreads();

    float* blkScr = g_qkv + (size_t)blockIdx.x * BLK_W;
    #pragma unroll 1
    for (int nc = 0; nc < 3; ++nc) {
        float acc[4][4][4] = {};
        gemm64(acc, g_wtf + nc * DIM * DIM, sVX, sW, swByte, tid, g, tig, wid * 32);
        // Write fragments transposed: scratch[sec][col][token]
        float* dst = blkScr + nc * SEC_W;
        #pragma unroll
        for (int mf = 0; mf < 4; ++mf) {
            #pragma unroll
            for (int j = 0; j < 4; ++j) {
                int col = wid * 32 + j * 8 + 2 * tig;
                int r0 = mf * 16 + g, r1 = r0 + 8;
                dst[col * BT + r0]       = acc[mf][j][0];
                dst[(col + 1) * BT + r0] = acc[mf][j][1];
                dst[col * BT + r1]       = acc[mf][j][2];
                dst[(col + 1) * BT + r1] = acc[mf][j][3];
            }
        }
    }
}

// ================= K2: heads-attention + output projection ==================
__global__ void __launch_bounds__(NTH, 2)
sa_attn_out_kernel(const float* __restrict__ bp, float* __restrict__ out) {
    extern __shared__ char smem[];
    uint32_t* sVX = reinterpret_cast<uint32_t*>(smem + OFF_VX);   // x tile (tf32)
    uint32_t* sW  = reinterpret_cast<uint32_t*>(smem + OFF_W);
    uint32_t swByte = (uint32_t)__cvta_generic_to_shared(smem + OFF_W);

    const int tid  = threadIdx.x;
    const int wid  = tid >> 5;
    const int lane = tid & 31;
    const int g    = lane >> 2;
    const int tig  = lane & 3;

    const float* blkScr = g_qkv + (size_t)blockIdx.x * BLK_W;

    // ---- Per-token heads-attention: warp = head (wid), 2 tokens per lane ---
    // Scratch is [col][token]; lane indexes token -> coalesced 128B loads.
    #pragma unroll 1
    for (int p = 0; p < BT / 32; ++p) {
        const int h = wid, t = p * 32 + lane;
        const float* qp = blkScr + (h * HD) * BT + t;
        const float* kp = blkScr + SEC_W + t;
        const float* vp = blkScr + 2 * SEC_W + t;

        float q[HD];
        #pragma unroll
        for (int d = 0; d < HD; ++d) q[d] = qp[d * BT];

        float a[NUM_H];
        float mx = -1e30f;
        #pragma unroll
        for (int gg = 0; gg < NUM_H; ++gg) {
            float s = 0.f;
            #pragma unroll
            for (int d = 0; d < HD; ++d) s += q[d] * kp[(gg * HD + d) * BT];
            s *= 0.17677669529663687f;   // 1/sqrt(32)
            a[gg] = s;
            mx = fmaxf(mx, s);
        }
        float sum = 0.f;
        #pragma unroll
        for (int gg = 0; gg < NUM_H; ++gg) { a[gg] = __expf(a[gg] - mx); sum += a[gg]; }
        float inv = 1.f / sum;
        #pragma unroll
        for (int gg = 0; gg < NUM_H; ++gg) a[gg] *= inv;

        uint32_t* xp = sVX + t * STR_VX + h * HD;
        #pragma unroll
        for (int d = 0; d < HD; ++d) {
            float s = 0.f;
            #pragma unroll
            for (int gg = 0; gg < NUM_H; ++gg) s += a[gg] * vp[(gg * HD + d) * BT];
            xp[d] = f2tf(s);
        }
    }
    __syncthreads();

    // ---- out = x @ Wp + bp
    {
        float acc[4][4][4] = {};
        gemm64(acc, g_wtf + 3 * DIM * DIM, sVX, sW, swByte, tid, g, tig, wid * 32);

        float bias[4][2];
        #pragma unroll
        for (int j = 0; j < 4; ++j) {
            int n = wid * 32 + j * 8 + 2 * tig;
            bias[j][0] = bp[n];
            bias[j][1] = bp[n + 1];
        }
        float* outBlk = out + (size_t)blockIdx.x * BT * DIM;
        #pragma unroll
        for (int mf = 0; mf < 4; ++mf) {
            #pragma unroll
            for (int j = 0; j < 4; ++j) {
                int row = mf * 16 + g;
                int n = wid * 32 + j * 8 + 2 * tig;
                float2 lo = make_float2(acc[mf][j][0] + bias[j][0],
                                        acc[mf][j][1] + bias[j][1]);
                float2 hi = make_float2(acc[mf][j][2] + bias[j][0],
                                        acc[mf][j][3] + bias[j][1]);
                *reinterpret_cast<float2*>(outBlk + (size_t)row * DIM + n)       = lo;
                *reinterpret_cast<float2*>(outBlk + (size_t)(row + 8) * DIM + n) = hi;
            }
        }
    }
}

extern "C" void kernel_launch(void* const* d_in, const int* in_sizes, int n_in,
                              void* d_out, int out_size) {
    const float* v  = (const float*)d_in[0];
    const float* Wq = (const float*)d_in[1];
    const float* Wk = (const float*)d_in[2];
    const float* Wv = (const float*)d_in[3];
    const float* Wp = (const float*)d_in[4];
    const float* bp = (const float*)d_in[5];
    float* out = (float*)d_out;

    cudaFuncSetAttribute(sa_qkv_kernel,
                         cudaFuncAttributeMaxDynamicSharedMemorySize, SMEM_BYTES);
    cudaFuncSetAttribute(sa_attn_out_kernel,
                         cudaFuncAttributeMaxDynamicSharedMemorySize, SMEM_BYTES);

    int M = in_sizes[0] / DIM;          // 65536 tokens
    int grid = M / BT;                  // 1024 CTAs
    cvt_weights_kernel<<<DIM * DIM / 4 / NTH, NTH>>>(Wq, Wk, Wv, Wp);
    sa_qkv_kernel<<<grid, NTH, SMEM_BYTES>>>(v);
    sa_attn_out_kernel<<<grid, NTH, SMEM_BYTES>>>(bp, out);
}

// round 11
// speedup vs baseline: 1.8669x; 1.1858x over previous
#include <cuda_runtime.h>
#include <cstdint>

// ---------------------------------------------------------------------------
// Fused SelfAttention (attention over heads axis), 3 kernels (R11):
//   K0: weights fp32 -> tf32 once
//   K1: qkv = v @ {Wq,Wk,Wv} -> scratch (transposed per 64-token block)
//   K2: per-token 8x8 heads softmax-attention + out = x @ Wp + bp
// R11: BARRIER-FREE GEMM. Each warp stages its own 32 weight columns with
// warp-private cp.async commit groups (sVX is read-only), so the chunk loop
// has no __syncthreads at all. A-fragments loaded via ldmatrix.x4 (1 LDSM
// replaces 4 LDS.32), cutting issue slots and address ALU.
// ---------------------------------------------------------------------------

#define NUM_H   8
#define HD      32
#define DIM     256
#define BT      64      // tokens per CTA
#define NTH     256     // threads per CTA (8 warps)
#define KC      16      // K-chunk rows per weight buffer (double-buffered)
#define NCHUNK  (DIM / KC)   // 16

// SMEM strides (words): STR_VX%32==4 -> ldmatrix tiles conflict-free,
// STR_W%32==8 -> B-fragment LDS conflict-free.
#define STR_VX  260
#define STR_W   264

#define OFF_VX  0
#define OFF_W   (BT * STR_VX * 4)            // 66560
#define WBUF_W  (KC * STR_W)                 // 4224 words per buffer
#define WBUF_B  (WBUF_W * 4)                 // 16896 bytes
#define SMEM_BYTES (OFF_W + 2 * WBUF_B)      // 100352 bytes -> 2 CTAs/SM

// qkv scratch: per 64-token block, 3 sections (q|k|vv), each [256 cols][64 tok]
#define SEC_W    (DIM * BT)                  // 16384 words
#define BLK_W    (3 * SEC_W)                 // 49152 words
#define NBLK     1024
__device__ float    g_qkv[(size_t)NBLK * BLK_W];   // 192 MiB scratch
__device__ uint32_t g_wtf[4 * DIM * DIM];          // tf32 weights: q,k,v,p

__device__ __forceinline__ uint32_t f2tf(float f) {
    uint32_t u;
    asm("cvt.rna.tf32.f32 %0, %1;" : "=r"(u) : "f"(f));
    return u;
}

__device__ __forceinline__ void mma_tf32(float d[4], const uint32_t a[4], const uint32_t b[2]) {
    asm volatile(
        "mma.sync.aligned.m16n8k8.row.col.f32.tf32.tf32.f32 "
        "{%0,%1,%2,%3}, {%4,%5,%6,%7}, {%8,%9}, {%0,%1,%2,%3};"
        : "+f"(d[0]), "+f"(d[1]), "+f"(d[2]), "+f"(d[3])
        : "r"(a[0]), "r"(a[1]), "r"(a[2]), "r"(a[3]), "r"(b[0]), "r"(b[1]));
}

__device__ __forceinline__ void ldsm4(uint32_t a[4], uint32_t saddr) {
    asm volatile("ldmatrix.sync.aligned.m8n8.x4.shared.b16 {%0,%1,%2,%3}, [%4];"
                 : "=r"(a[0]), "=r"(a[1]), "=r"(a[2]), "=r"(a[3]) : "r"(saddr));
}

__device__ __forceinline__ void cp16(uint32_t dst, const void* src) {
    asm volatile("cp.async.cg.shared.global [%0], [%1], 16;" :: "r"(dst), "l"(src));
}
#define CP_COMMIT()  asm volatile("cp.async.commit_group;")
#define CP_WAIT(n)   asm volatile("cp.async.wait_group %0;" :: "n"(n))

// Warp-private: stage this warp's 32 columns (nb..nb+31) of one [KC x 256]
// weight chunk. 16 rows x 128B; lane l, step i: unit u = l + 32*i ->
// row u>>3, 16B-unit u&7. Gmem fully coalesced (8 lanes per 128B row slice).
__device__ __forceinline__ void issue_chunk_warp(uint32_t swByte,
                                                 const uint32_t* __restrict__ Wtf,
                                                 int kc, int nb, int lane) {
    const uint32_t* src = Wtf + (size_t)kc * KC * DIM + nb;
    #pragma unroll
    for (int i = 0; i < 4; ++i) {
        int u  = lane + 32 * i;
        int r  = u >> 3;
        int c16 = u & 7;
        cp16(swByte + (uint32_t)(r * STR_W + nb + c16 * 4) * 4,
             src + (size_t)r * DIM + c16 * 4);
    }
}

// KC/8 k-steps of m16n8k8: 4 m-frags (64 rows) x 4 n-frags (32 cols).
// A via ldmatrix.x4 (thread's lane-addr precomputed), B via LDS.32.
__device__ __forceinline__ void mma_chunk(float acc[4][4][4],
                                          uint32_t svxS, int aRowCol,  // precomp lane offset
                                          const uint32_t* __restrict__ sW,
                                          int g, int tig, int nb, int kbase) {
    #pragma unroll
    for (int k8 = 0; k8 < KC / 8; ++k8) {
        int c = kbase + k8 * 8;
        uint32_t a[4][4];
        #pragma unroll
        for (int mf = 0; mf < 4; ++mf)
            ldsm4(a[mf], svxS + (uint32_t)((mf * 16) * STR_VX + c + aRowCol) * 4);
        #pragma unroll
        for (int j = 0; j < 4; ++j) {
            int n = nb + j * 8 + g;
            uint32_t b[2];
            b[0] = sW[(k8 * 8 + tig) * STR_W + n];
            b[1] = sW[(k8 * 8 + tig + 4) * STR_W + n];
            #pragma unroll
            for (int mf = 0; mf < 4; ++mf) mma_tf32(acc[mf][j], a[mf], b);
        }
    }
}

// 64x256x256 GEMM, barrier-free: each warp pipelines its own B columns.
__device__ __forceinline__ void gemm64(float acc[4][4][4], const uint32_t* __restrict__ Wtf,
                                       uint32_t svxS, int aRowCol,
                                       const uint32_t* __restrict__ sW, uint32_t swByte,
                                       int lane, int g, int tig, int nb) {
    issue_chunk_warp(swByte, Wtf, 0, nb, lane);           CP_COMMIT();
    issue_chunk_warp(swByte + WBUF_B, Wtf, 1, nb, lane);  CP_COMMIT();
    #pragma unroll 1
    for (int kc = 0; kc < NCHUNK; ++kc) {
        if (kc < NCHUNK - 1) { CP_WAIT(1); } else { CP_WAIT(0); }
        mma_chunk(acc, svxS, aRowCol, sW + (kc & 1) * WBUF_W, g, tig, nb, kc * KC);
        if (kc + 2 < NCHUNK) {
            issue_chunk_warp(swByte + (kc & 1) * WBUF_B, Wtf, kc + 2, nb, lane);
            CP_COMMIT();
        }
    }
}

// ==================== K0: convert weights fp32 -> tf32 ======================
__global__ void __launch_bounds__(NTH)
cvt_weights_kernel(const float* __restrict__ Wq, const float* __restrict__ Wk,
                   const float* __restrict__ Wv, const float* __restrict__ Wp) {
    int f = blockIdx.x * NTH + threadIdx.x;      // float4 index, 16384/matrix
    const float* srcs[4] = {Wq, Wk, Wv, Wp};
    uint4* dst = reinterpret_cast<uint4*>(g_wtf);
    #pragma unroll
    for (int m = 0; m < 4; ++m) {
        float4 x = reinterpret_cast<const float4*>(srcs[m])[f];
        dst[m * (DIM * DIM / 4) + f] =
            make_uint4(f2tf(x.x), f2tf(x.y), f2tf(x.z), f2tf(x.w));
    }
}

// ========================= K1: qkv projections ==============================
__global__ void __launch_bounds__(NTH, 2)
sa_qkv_kernel(const float* __restrict__ v) {
    extern __shared__ char smem[];
    uint32_t* sVX = reinterpret_cast<uint32_t*>(smem + OFF_VX);
    uint32_t* sW  = reinterpret_cast<uint32_t*>(smem + OFF_W);
    uint32_t svxS   = (uint32_t)__cvta_generic_to_shared(smem + OFF_VX);
    uint32_t swByte = (uint32_t)__cvta_generic_to_shared(smem + OFF_W);

    const int tid  = threadIdx.x;
    const int wid  = tid >> 5;
    const int lane = tid & 31;
    const int g    = lane >> 2;
    const int tig  = lane & 3;
    // ldmatrix lane address component: tile t=lane>>3;
    // row-in-mf = (t&1)*8 + (lane&7); col offset = (t>>1)*4.
    const int t4   = lane >> 3;
    const int aRowCol = ((t4 & 1) * 8 + (lane & 7)) * STR_VX + (t4 >> 1) * 4;

    // Stage v tile [64 x 256] -> tf32
    {
        const float4* src = reinterpret_cast<const float4*>(v + (size_t)blockIdx.x * BT * DIM);
        #pragma unroll
        for (int i = 0; i < (BT * DIM / 4) / NTH; ++i) {   // 16 per thread
            int f  = tid + i * NTH;
            int r  = f >> 6;
            int c4 = f & 63;
            float4 x = src[f];
            uint4 u = make_uint4(f2tf(x.x), f2tf(x.y), f2tf(x.z), f2tf(x.w));
            *reinterpret_cast<uint4*>(sVX + r * STR_VX + c4 * 4) = u;
        }
    }
    __syncthreads();    // only CTA-wide barrier in this kernel

    float* blkScr = g_qkv + (size_t)blockIdx.x * BLK_W;
    #pragma unroll 1
    for (int nc = 0; nc < 3; ++nc) {
        float acc[4][4][4] = {};
        gemm64(acc, g_wtf + nc * DIM * DIM, svxS, aRowCol, sW, swByte,
               lane, g, tig, wid * 32);
        // Write fragments transposed: scratch[sec][col][token]
        float* dst = blkScr + nc * SEC_W;
        #pragma unroll
        for (int mf = 0; mf < 4; ++mf) {
            #pragma unroll
            for (int j = 0; j < 4; ++j) {
                int col = wid * 32 + j * 8 + 2 * tig;
                int r0 = mf * 16 + g, r1 = r0 + 8;
                dst[col * BT + r0]       = acc[mf][j][0];
                dst[(col + 1) * BT + r0] = acc[mf][j][1];
                dst[col * BT + r1]       = acc[mf][j][2];
                dst[(col + 1) * BT + r1] = acc[mf][j][3];
            }
        }
    }
}

// ================= K2: heads-attention + output projection ==================
__global__ void __launch_bounds__(NTH, 2)
sa_attn_out_kernel(const float* __restrict__ bp, float* __restrict__ out) {
    extern __shared__ char smem[];
    uint32_t* sVX = reinterpret_cast<uint32_t*>(smem + OFF_VX);   // x tile (tf32)
    uint32_t* sW  = reinterpret_cast<uint32_t*>(smem + OFF_W);
    uint32_t svxS   = (uint32_t)__cvta_generic_to_shared(smem + OFF_VX);
    uint32_t swByte = (uint32_t)__cvta_generic_to_shared(smem + OFF_W);

    const int tid  = threadIdx.x;
    const int wid  = tid >> 5;
    const int lane = tid & 31;
    const int g    = lane >> 2;
    const int tig  = lane & 3;
    const int t4   = lane >> 3;
    const int aRowCol = ((t4 & 1) * 8 + (lane & 7)) * STR_VX + (t4 >> 1) * 4;

    const float* blkScr = g_qkv + (size_t)blockIdx.x * BLK_W;

    // ---- Per-token heads-attention: warp = head (wid), 2 tokens per lane ---
    // Scratch is [col][token]; lane indexes token -> coalesced 128B loads.
    #pragma unroll 1
    for (int p = 0; p < BT / 32; ++p) {
        const int h = wid, t = p * 32 + lane;
        const float* qp = blkScr + (h * HD) * BT + t;
        const float* kp = blkScr + SEC_W + t;
        const float* vp = blkScr + 2 * SEC_W + t;

        float q[HD];
        #pragma unroll
        for (int d = 0; d < HD; ++d) q[d] = qp[d * BT];

        float a[NUM_H];
        float mx = -1e30f;
        #pragma unroll
        for (int gg = 0; gg < NUM_H; ++gg) {
            float s = 0.f;
            #pragma unroll
            for (int d = 0; d < HD; ++d) s += q[d] * kp[(gg * HD + d) * BT];
            s *= 0.17677669529663687f;   // 1/sqrt(32)
            a[gg] = s;
            mx = fmaxf(mx, s);
        }
        float sum = 0.f;
        #pragma unroll
        for (int gg = 0; gg < NUM_H; ++gg) { a[gg] = __expf(a[gg] - mx); sum += a[gg]; }
        float inv = 1.f / sum;
        #pragma unroll
        for (int gg = 0; gg < NUM_H; ++gg) a[gg] *= inv;

        uint32_t* xp = sVX + t * STR_VX + h * HD;
        #pragma unroll
        for (int d = 0; d < HD; ++d) {
            float s = 0.f;
            #pragma unroll
            for (int gg = 0; gg < NUM_H; ++gg) s += a[gg] * vp[(gg * HD + d) * BT];
            xp[d] = f2tf(s);
        }
    }
    __syncthreads();    // x tile complete before GEMM reads cross-warp rows

    // ---- out = x @ Wp + bp (barrier-free GEMM)
    {
        float acc[4][4][4] = {};
        gemm64(acc, g_wtf + 3 * DIM * DIM, svxS, aRowCol, sW, swByte,
               lane, g, tig, wid * 32);

        float bias[4][2];
        #pragma unroll
        for (int j = 0; j < 4; ++j) {
            int n = wid * 32 + j * 8 + 2 * tig;
            bias[j][0] = bp[n];
            bias[j][1] = bp[n + 1];
        }
        float* outBlk = out + (size_t)blockIdx.x * BT * DIM;
        #pragma unroll
        for (int mf = 0; mf < 4; ++mf) {
            #pragma unroll
            for (int j = 0; j < 4; ++j) {
                int row = mf * 16 + g;
                int n = wid * 32 + j * 8 + 2 * tig;
                float2 lo = make_float2(acc[mf][j][0] + bias[j][0],
                                        acc[mf][j][1] + bias[j][1]);
                float2 hi = make_float2(acc[mf][j][2] + bias[j][0],
                                        acc[mf][j][3] + bias[j][1]);
                *reinterpret_cast<float2*>(outBlk + (size_t)row * DIM + n)       = lo;
                *reinterpret_cast<float2*>(outBlk + (size_t)(row + 8) * DIM + n) = hi;
            }
        }
    }
}

extern "C" void kernel_launch(void* const* d_in, const int* in_sizes, int n_in,
                              void* d_out, int out_size) {
    const float* v  = (const float*)d_in[0];
    const float* Wq = (const float*)d_in[1];
    const float* Wk = (const float*)d_in[2];
    const float* Wv = (const float*)d_in[3];
    const float* Wp = (const float*)d_in[4];
    const float* bp = (const float*)d_in[5];
    float* out = (float*)d_out;

    cudaFuncSetAttribute(sa_qkv_kernel,
                         cudaFuncAttributeMaxDynamicSharedMemorySize, SMEM_BYTES);
    cudaFuncSetAttribute(sa_attn_out_kernel,
                         cudaFuncAttributeMaxDynamicSharedMemorySize, SMEM_BYTES);

    int M = in_sizes[0] / DIM;          // 65536 tokens
    int grid = M / BT;                  // 1024 CTAs
    cvt_weights_kernel<<<DIM * DIM / 4 / NTH, NTH>>>(Wq, Wk, Wv, Wp);
    sa_qkv_kernel<<<grid, NTH, SMEM_BYTES>>>(v);
    sa_attn_out_kernel<<<grid, NTH, SMEM_BYTES>>>(bp, out);
}

// round 14
// speedup vs baseline: 1.8671x; 1.0001x over previous
#include <cuda_runtime.h>
#include <cstdint>

// ---------------------------------------------------------------------------
// Fused SelfAttention (attention over heads axis), 3 kernels (R12):
//   K0: weights fp32 -> tf32 once
//   K1: qkv = v @ {Wq,Wk,Wv} -> scratch (transposed per 64-token block)
//   K2: per-token 8x8 heads softmax-attention + out = x @ Wp + bp
// R12: DEEP cp.async PIPELINE. KC=8 chunks in a 5-buffer ring, 4 chunks in
// flight per warp (covers ~260cyc L2 latency vs ~65cyc MMA/chunk). Still
// barrier-free (warp-private B columns), ldmatrix A-frags, 2 CTAs/SM.
// ---------------------------------------------------------------------------

#define NUM_H   8
#define HD      32
#define DIM     256
#define BT      64      // tokens per CTA
#define NTH     256     // threads per CTA (8 warps)
#define KC      8       // K-chunk rows per weight buffer
#define NCHUNK  (DIM / KC)   // 32
#define NBUF    5       // ring depth (4 chunks in flight + 1 in use)

// SMEM strides (words): STR_VX%32==4 -> ldmatrix tiles conflict-free,
// STR_W%32==8 -> B-fragment LDS conflict-free.
#define STR_VX  260
#define STR_W   264

#define OFF_VX  0
#define OFF_W   (BT * STR_VX * 4)            // 66560
#define WBUF_W  (KC * STR_W)                 // 2112 words per buffer
#define WBUF_B  (WBUF_W * 4)                 // 8448 bytes
#define SMEM_BYTES (OFF_W + NBUF * WBUF_B)   // 108800 bytes -> 2 CTAs/SM

// qkv scratch: per 64-token block, 3 sections (q|k|vv), each [256 cols][64 tok]
#define SEC_W    (DIM * BT)                  // 16384 words
#define BLK_W    (3 * SEC_W)                 // 49152 words
#define NBLK     1024
__device__ float    g_qkv[(size_t)NBLK * BLK_W];   // 192 MiB scratch
__device__ uint32_t g_wtf[4 * DIM * DIM];          // tf32 weights: q,k,v,p

__device__ __forceinline__ uint32_t f2tf(float f) {
    uint32_t u;
    asm("cvt.rna.tf32.f32 %0, %1;" : "=r"(u) : "f"(f));
    return u;
}

__device__ __forceinline__ void mma_tf32(float d[4], const uint32_t a[4], const uint32_t b[2]) {
    asm volatile(
        "mma.sync.aligned.m16n8k8.row.col.f32.tf32.tf32.f32 "
        "{%0,%1,%2,%3}, {%4,%5,%6,%7}, {%8,%9}, {%0,%1,%2,%3};"
        : "+f"(d[0]), "+f"(d[1]), "+f"(d[2]), "+f"(d[3])
        : "r"(a[0]), "r"(a[1]), "r"(a[2]), "r"(a[3]), "r"(b[0]), "r"(b[1]));
}

__device__ __forceinline__ void ldsm4(uint32_t a[4], uint32_t saddr) {
    asm volatile("ldmatrix.sync.aligned.m8n8.x4.shared.b16 {%0,%1,%2,%3}, [%4];"
                 : "=r"(a[0]), "=r"(a[1]), "=r"(a[2]), "=r"(a[3]) : "r"(saddr));
}

__device__ __forceinline__ void cp16(uint32_t dst, const void* src) {
    asm volatile("cp.async.cg.shared.global [%0], [%1], 16;" :: "r"(dst), "l"(src));
}
#define CP_COMMIT()  asm volatile("cp.async.commit_group;")
#define CP_WAIT(n)   asm volatile("cp.async.wait_group %0;" :: "n"(n))

// Warp-private: stage this warp's 32 columns (nb..nb+31) of one [KC x 256]
// weight chunk (8 rows x 128B slice -> 64 x 16B units, 2 per lane).
__device__ __forceinline__ void issue_chunk_warp(uint32_t swByte,
                                                 const uint32_t* __restrict__ Wtf,
                                                 int kc, int nb, int lane) {
    const uint32_t* src = Wtf + (size_t)kc * KC * DIM + nb;
    #pragma unroll
    for (int i = 0; i < 2; ++i) {
        int u   = lane + 32 * i;      // 0..63
        int r   = u >> 3;             // 0..7
        int c16 = u & 7;              // 16B unit within 128B row slice
        cp16(swByte + (uint32_t)(r * STR_W + nb + c16 * 4) * 4,
             src + (size_t)r * DIM + c16 * 4);
    }
}

// One KC=8 chunk = 1 k-step of m16n8k8: 4 m-frags (64 rows) x 4 n-frags.
__device__ __forceinline__ void mma_chunk(float acc[4][4][4],
                                          uint32_t svxS, int aRowCol,
                                          const uint32_t* __restrict__ sW,
                                          int g, int tig, int nb, int kbase) {
    uint32_t a[4][4];
    #pragma unroll
    for (int mf = 0; mf < 4; ++mf)
        ldsm4(a[mf], svxS + (uint32_t)((mf * 16) * STR_VX + kbase + aRowCol) * 4);
    #pragma unroll
    for (int j = 0; j < 4; ++j) {
        int n = nb + j * 8 + g;
        uint32_t b[2];
        b[0] = sW[tig * STR_W + n];
        b[1] = sW[(tig + 4) * STR_W + n];
        #pragma unroll
        for (int mf = 0; mf < 4; ++mf) mma_tf32(acc[mf][j], a[mf], b);
    }
}

// 64x256x256 GEMM, barrier-free, 5-buffer ring, 4 chunks in flight.
__device__ __forceinline__ void gemm64(float acc[4][4][4], const uint32_t* __restrict__ Wtf,
                                       uint32_t svxS, int aRowCol,
                                       const uint32_t* __restrict__ sW, uint32_t swByte,
                                       int lane, int g, int tig, int nb) {
    #pragma unroll
    for (int p = 0; p < 4; ++p) {
        issue_chunk_warp(swByte + p * WBUF_B, Wtf, p, nb, lane);
        CP_COMMIT();
    }
    int buf = 0, nbuf = 4 % NBUF;
    #pragma unroll 1
    for (int kc = 0; kc < NCHUNK; ++kc) {
        int rem = NCHUNK - 1 - kc;            // chunks still to consume after this
        if (rem >= 3)      { CP_WAIT(3); }
        else if (rem == 2) { CP_WAIT(2); }
        else if (rem == 1) { CP_WAIT(1); }
        else               { CP_WAIT(0); }
        mma_chunk(acc, svxS, aRowCol, sW + buf * WBUF_W, g, tig, nb, kc * KC);
        if (kc + 4 < NCHUNK) {
            issue_chunk_warp(swByte + nbuf * WBUF_B, Wtf, kc + 4, nb, lane);
            CP_COMMIT();
        }
        if (++buf == NBUF)  buf = 0;
        if (++nbuf == NBUF) nbuf = 0;
    }
}

// ==================== K0: convert weights fp32 -> tf32 ======================
__global__ void __launch_bounds__(NTH)
cvt_weights_kernel(const float* __restrict__ Wq, const float* __restrict__ Wk,
                   const float* __restrict__ Wv, const float* __restrict__ Wp) {
    int f = blockIdx.x * NTH + threadIdx.x;      // float4 index, 16384/matrix
    const float* srcs[4] = {Wq, Wk, Wv, Wp};
    uint4* dst = reinterpret_cast<uint4*>(g_wtf);
    #pragma unroll
    for (int m = 0; m < 4; ++m) {
        float4 x = reinterpret_cast<const float4*>(srcs[m])[f];
        dst[m * (DIM * DIM / 4) + f] =
            make_uint4(f2tf(x.x), f2tf(x.y), f2tf(x.z), f2tf(x.w));
    }
}

// ========================= K1: qkv projections ==============================
__global__ void __launch_bounds__(NTH, 2)
sa_qkv_kernel(const float* __restrict__ v) {
    extern __shared__ char smem[];
    uint32_t* sVX = reinterpret_cast<uint32_t*>(smem + OFF_VX);
    uint32_t* sW  = reinterpret_cast<uint32_t*>(smem + OFF_W);
    uint32_t svxS   = (uint32_t)__cvta_generic_to_shared(smem + OFF_VX);
    uint32_t swByte = (uint32_t)__cvta_generic_to_shared(smem + OFF_W);

    const int tid  = threadIdx.x;
    const int wid  = tid >> 5;
    const int lane = tid & 31;
    const int g    = lane >> 2;
    const int tig  = lane & 3;
    // ldmatrix lane address: tile t4=lane>>3; row = (t4&1)*8 + (lane&7),
    // col offset (t4>>1)*4.
    const int t4   = lane >> 3;
    const int aRowCol = ((t4 & 1) * 8 + (lane & 7)) * STR_VX + (t4 >> 1) * 4;

    // Stage v tile [64 x 256] -> tf32
    {
        const float4* src = reinterpret_cast<const float4*>(v + (size_t)blockIdx.x * BT * DIM);
        #pragma unroll
        for (int i = 0; i < (BT * DIM / 4) / NTH; ++i) {   // 16 per thread
            int f  = tid + i * NTH;
            int r  = f >> 6;
            int c4 = f & 63;
            float4 x = src[f];
            uint4 u = make_uint4(f2tf(x.x), f2tf(x.y), f2tf(x.z), f2tf(x.w));
            *reinterpret_cast<uint4*>(sVX + r * STR_VX + c4 * 4) = u;
        }
    }
    __syncthreads();    // only CTA-wide barrier in this kernel

    float* blkScr = g_qkv + (size_t)blockIdx.x * BLK_W;
    #pragma unroll 1
    for (int nc = 0; nc < 3; ++nc) {
        float acc[4][4][4] = {};
        gemm64(acc, g_wtf + nc * DIM * DIM, svxS, aRowCol, sW, swByte,
               lane, g, tig, wid * 32);
        // Write fragments transposed: scratch[sec][col][token]
        float* dst = blkScr + nc * SEC_W;
        #pragma unroll
        for (int mf = 0; mf < 4; ++mf) {
            #pragma unroll
            for (int j = 0; j < 4; ++j) {
                int col = wid * 32 + j * 8 + 2 * tig;
                int r0 = mf * 16 + g, r1 = r0 + 8;
                dst[col * BT + r0]       = acc[mf][j][0];
                dst[(col + 1) * BT + r0] = acc[mf][j][1];
                dst[col * BT + r1]       = acc[mf][j][2];
                dst[(col + 1) * BT + r1] = acc[mf][j][3];
            }
        }
    }
}

// ================= K2: heads-attention + output projection ==================
__global__ void __launch_bounds__(NTH, 2)
sa_attn_out_kernel(const float* __restrict__ bp, float* __restrict__ out) {
    extern __shared__ char smem[];
    uint32_t* sVX = reinterpret_cast<uint32_t*>(smem + OFF_VX);   // x tile (tf32)
    uint32_t* sW  = reinterpret_cast<uint32_t*>(smem + OFF_W);
    uint32_t svxS   = (uint32_t)__cvta_generic_to_shared(smem + OFF_VX);
    uint32_t swByte = (uint32_t)__cvta_generic_to_shared(smem + OFF_W);

    const int tid  = threadIdx.x;
    const int wid  = tid >> 5;
    const int lane = tid & 31;
    const int g    = lane >> 2;
    const int tig  = lane & 3;
    const int t4   = lane >> 3;
    const int aRowCol = ((t4 & 1) * 8 + (lane & 7)) * STR_VX + (t4 >> 1) * 4;

    const float* blkScr = g_qkv + (size_t)blockIdx.x * BLK_W;

    // ---- Per-token heads-attention: warp = head (wid), 2 tokens per lane ---
    // Scratch is [col][token]; lane indexes token -> coalesced 128B loads.
    #pragma unroll 1
    for (int p = 0; p < BT / 32; ++p) {
        const int h = wid, t = p * 32 + lane;
        const float* qp = blkScr + (h * HD) * BT + t;
        const float* kp = blkScr + SEC_W + t;
        const float* vp = blkScr + 2 * SEC_W + t;

        float q[HD];
        #pragma unroll
        for (int d = 0; d < HD; ++d) q[d] = qp[d * BT];

        float a[NUM_H];
        float mx = -1e30f;
        #pragma unroll
        for (int gg = 0; gg < NUM_H; ++gg) {
            float s = 0.f;
            #pragma unroll
            for (int d = 0; d < HD; ++d) s += q[d] * kp[(gg * HD + d) * BT];
            s *= 0.17677669529663687f;   // 1/sqrt(32)
            a[gg] = s;
            mx = fmaxf(mx, s);
        }
        float sum = 0.f;
        #pragma unroll
        for (int gg = 0; gg < NUM_H; ++gg) { a[gg] = __expf(a[gg] - mx); sum += a[gg]; }
        float inv = 1.f / sum;
        #pragma unroll
        for (int gg = 0; gg < NUM_H; ++gg) a[gg] *= inv;

        uint32_t* xp = sVX + t * STR_VX + h * HD;
        #pragma unroll
        for (int d = 0; d < HD; ++d) {
            float s = 0.f;
            #pragma unroll
            for (int gg = 0; gg < NUM_H; ++gg) s += a[gg] * vp[(gg * HD + d) * BT];
            xp[d] = f2tf(s);
        }
    }
    __syncthreads();    // x tile complete before GEMM reads cross-warp rows

    // ---- out = x @ Wp + bp (barrier-free GEMM)
    {
        float acc[4][4][4] = {};
        gemm64(acc, g_wtf + 3 * DIM * DIM, svxS, aRowCol, sW, swByte,
               lane, g, tig, wid * 32);

        float bias[4][2];
        #pragma unroll
        for (int j = 0; j < 4; ++j) {
            int n = wid * 32 + j * 8 + 2 * tig;
            bias[j][0] = bp[n];
            bias[j][1] = bp[n + 1];
        }
        float* outBlk = out + (size_t)blockIdx.x * BT * DIM;
        #pragma unroll
        for (int mf = 0; mf < 4; ++mf) {
            #pragma unroll
            for (int j = 0; j < 4; ++j) {
                int row = mf * 16 + g;
                int n = wid * 32 + j * 8 + 2 * tig;
                float2 lo = make_float2(acc[mf][j][0] + bias[j][0],
                                        acc[mf][j][1] + bias[j][1]);
                float2 hi = make_float2(acc[mf][j][2] + bias[j][0],
                                        acc[mf][j][3] + bias[j][1]);
                *reinterpret_cast<float2*>(outBlk + (size_t)row * DIM + n)       = lo;
                *reinterpret_cast<float2*>(outBlk + (size_t)(row + 8) * DIM + n) = hi;
            }
        }
    }
}

extern "C" void kernel_launch(void* const* d_in, const int* in_sizes, int n_in,
                              void* d_out, int out_size) {
    const float* v  = (const float*)d_in[0];
    const float* Wq = (const float*)d_in[1];
    const float* Wk = (const float*)d_in[2];
    const float* Wv = (const float*)d_in[3];
    const float* Wp = (const float*)d_in[4];
    const float* bp = (const float*)d_in[5];
    float* out = (float*)d_out;

    cudaFuncSetAttribute(sa_qkv_kernel,
                         cudaFuncAttributeMaxDynamicSharedMemorySize, SMEM_BYTES);
    cudaFuncSetAttribute(sa_attn_out_kernel,
                         cudaFuncAttributeMaxDynamicSharedMemorySize, SMEM_BYTES);

    int M = in_sizes[0] / DIM;          // 65536 tokens
    int grid = M / BT;                  // 1024 CTAs
    cvt_weights_kernel<<<DIM * DIM / 4 / NTH, NTH>>>(Wq, Wk, Wv, Wp);
    sa_qkv_kernel<<<grid, NTH, SMEM_BYTES>>>(v);
    sa_attn_out_kernel<<<grid, NTH, SMEM_BYTES>>>(bp, out);
}

// round 17
// speedup vs baseline: 2.3523x; 1.2599x over previous
#include <cuda_runtime.h>
#include <cuda_fp16.h>
#include <cstdint>

// ---------------------------------------------------------------------------
// Fused SelfAttention (attention over heads axis), 3 kernels (R16):
//   K0: weights fp32 -> fp16, TRANSPOSED to [n][k]
//   K1: qkv = v @ {Wq,Wk,Wv} -> scratch (transposed per 64-token block)
//   K2: per-token 8x8 heads softmax-attention + out = x @ Wp + bp
// R16: tf32 m16n8k8 -> fp16 m16n8k16 (same 10 mantissa bits, 2x K per MMA).
// Halves MMA instruction count AND all smem/L1/cp.async byte traffic.
// Barrier-free warp-private weight pipelines, ldmatrix A-frags, 2 CTAs/SM.
// ---------------------------------------------------------------------------

#define NUM_H   8
#define HD      32
#define DIM     256
#define BT      64      // tokens per CTA
#define NTH     256     // threads per CTA (8 warps)
#define KCH     64      // k-halves per weight chunk
#define NCHUNK  (DIM / KCH)   // 4

#define STR_AH  264     // halves per A row (256 + 8 pad) -> ldmatrix conflict-free
#define A_BYTES (BT * STR_AH * 2)            // 33792
#define OFF_W   A_BYTES
#define WROW_W  36      // words per n-row in a chunk buffer (32 k-words + 4 pad)
#define WBUF_W  (DIM * WROW_W)               // 9216 words per buffer
#define WBUF_B  (WBUF_W * 4)                 // 36864 bytes
#define SMEM_BYTES (A_BYTES + 2 * WBUF_B)    // 107520 -> 2 CTAs/SM

// qkv scratch: per 64-token block, 3 sections (q|k|vv), each [256 cols][64 tok]
#define SEC_W    (DIM * BT)                  // 16384 words
#define BLK_W    (3 * SEC_W)                 // 49152 words
#define NBLK     1024
__device__ __align__(16) float  g_qkv[(size_t)NBLK * BLK_W];   // 192 MiB scratch
__device__ __align__(16) __half g_wth[4 * DIM * DIM];          // fp16 W^T [n][k]

__device__ __forceinline__ void mma_f16(float d[4], const uint32_t a[4], const uint32_t b[2]) {
    asm volatile(
        "mma.sync.aligned.m16n8k16.row.col.f32.f16.f16.f32 "
        "{%0,%1,%2,%3}, {%4,%5,%6,%7}, {%8,%9}, {%0,%1,%2,%3};"
        : "+f"(d[0]), "+f"(d[1]), "+f"(d[2]), "+f"(d[3])
        : "r"(a[0]), "r"(a[1]), "r"(a[2]), "r"(a[3]), "r"(b[0]), "r"(b[1]));
}

__device__ __forceinline__ void ldsm4(uint32_t a[4], uint32_t saddr) {
    asm volatile("ldmatrix.sync.aligned.m8n8.x4.shared.b16 {%0,%1,%2,%3}, [%4];"
                 : "=r"(a[0]), "=r"(a[1]), "=r"(a[2]), "=r"(a[3]) : "r"(saddr));
}

__device__ __forceinline__ void cp16(uint32_t dst, const void* src) {
    asm volatile("cp.async.cg.shared.global [%0], [%1], 16;" :: "r"(dst), "l"(src));
}
#define CP_COMMIT()  asm volatile("cp.async.commit_group;")
#define CP_WAIT(n)   asm volatile("cp.async.wait_group %0;" :: "n"(n) : "memory")

// Warp-private: stage this warp's 32 n-rows (nb..nb+31) of one chunk
// ([32 n][KCH=64 halves] = 32 x 128B). 8 x 16B units per n-row, 8 per lane.
__device__ __forceinline__ void issue_chunk_warp(uint32_t swByte,
                                                 const __half* __restrict__ Wt,
                                                 int kc, int nb, int lane) {
    const __half* src = Wt + (size_t)nb * DIM + kc * KCH;
    #pragma unroll
    for (int i = 0; i < 8; ++i) {
        int e  = lane + 32 * i;       // 0..255
        int nl = e >> 3;              // local n-row 0..31
        int u  = e & 7;               // 16B unit within 128B row slice
        cp16(swByte + (uint32_t)((nb + nl) * WROW_W + u * 4) * 4,
             src + (size_t)nl * DIM + u * 8);
    }
}

// One KCH=64 chunk = 4 k-steps of m16n8k16: 4 m-frags (64 rows) x 4 n-frags.
__device__ __forceinline__ void mma_chunk(float acc[4][4][4],
                                          uint32_t svxS, int laneOffB,
                                          const uint32_t* __restrict__ sWw,
                                          int g, int tig, int nb, int kcBaseH) {
    #pragma unroll
    for (int ks = 0; ks < KCH / 16; ++ks) {
        uint32_t a[4][4];
        #pragma unroll
        for (int mf = 0; mf < 4; ++mf)
            ldsm4(a[mf], svxS + (uint32_t)((mf * 16) * STR_AH + kcBaseH + ks * 16) * 2
                              + laneOffB);
        #pragma unroll
        for (int j = 0; j < 4; ++j) {
            int n = nb + j * 8 + g;
            uint32_t b[2];
            b[0] = sWw[n * WROW_W + ks * 8 + tig];
            b[1] = sWw[n * WROW_W + ks * 8 + 4 + tig];
            #pragma unroll
            for (int mf = 0; mf < 4; ++mf) mma_f16(acc[mf][j], a[mf], b);
        }
    }
}

// 64x256x256 GEMM, barrier-free: warp-private double-buffered weight chunks.
__device__ __forceinline__ void gemm64(float acc[4][4][4], const __half* __restrict__ Wt,
                                       uint32_t svxS, int laneOffB,
                                       const uint32_t* __restrict__ sWw, uint32_t swByte,
                                       int lane, int g, int tig, int nb) {
    issue_chunk_warp(swByte, Wt, 0, nb, lane);           CP_COMMIT();
    issue_chunk_warp(swByte + WBUF_B, Wt, 1, nb, lane);  CP_COMMIT();
    #pragma unroll 1
    for (int kc = 0; kc < NCHUNK; ++kc) {
        if (kc < NCHUNK - 1) { CP_WAIT(1); } else { CP_WAIT(0); }
        mma_chunk(acc, svxS, laneOffB, sWw + (kc & 1) * WBUF_W, g, tig, nb, kc * KCH);
        if (kc + 2 < NCHUNK) {
            issue_chunk_warp(swByte + (kc & 1) * WBUF_B, Wt, kc + 2, nb, lane);
            CP_COMMIT();
        }
    }
}

// ============ K0: transpose + convert weights to fp16 [n][k] ===============
__global__ void __launch_bounds__(NTH)
wt_transpose_kernel(const float* __restrict__ Wq, const float* __restrict__ Wk,
                    const float* __restrict__ Wv, const float* __restrict__ Wp) {
    __shared__ float tile[32][33];
    int m  = blockIdx.x >> 6;          // matrix
    int ti = (blockIdx.x & 63) >> 3;   // k-block
    int tj = blockIdx.x & 7;           // n-block
    const float* src = (m == 0) ? Wq : (m == 1) ? Wk : (m == 2) ? Wv : Wp;
    int c = threadIdx.x & 31, r0 = (threadIdx.x >> 5) * 4;
    #pragma unroll
    for (int rr = 0; rr < 4; ++rr)
        tile[r0 + rr][c] = src[(size_t)(ti * 32 + r0 + rr) * DIM + tj * 32 + c];
    __syncthreads();
    #pragma unroll
    for (int rr = 0; rr < 4; ++rr)
        g_wth[(size_t)m * DIM * DIM + (size_t)(tj * 32 + r0 + rr) * DIM + ti * 32 + c] =
            __float2half_rn(tile[c][r0 + rr]);
}

// ========================= K1: qkv projections ==============================
__global__ void __launch_bounds__(NTH, 2)
sa_qkv_kernel(const float* __restrict__ v) {
    extern __shared__ char smem[];
    uint32_t* sWw = reinterpret_cast<uint32_t*>(smem + OFF_W);
    const uint32_t svxS   = (uint32_t)__cvta_generic_to_shared(smem);
    const uint32_t swByte = (uint32_t)__cvta_generic_to_shared(smem + OFF_W);

    const int tid  = threadIdx.x;
    const int wid  = tid >> 5;
    const int lane = tid & 31;
    const int g    = lane >> 2;
    const int tig  = lane & 3;
    // ldmatrix lane offset (bytes): tile t4=lane>>3; row=(t4&1)*8+(lane&7),
    // half-col offset (t4>>1)*8.
    const int t4   = lane >> 3;
    const int laneOffB = (((t4 & 1) * 8 + (lane & 7)) * STR_AH + (t4 >> 1) * 8) * 2;

    // Stage v tile [64 x 256] -> fp16
    {
        __half* sA = reinterpret_cast<__half*>(smem);
        const float4* src = reinterpret_cast<const float4*>(v + (size_t)blockIdx.x * BT * DIM);
        #pragma unroll
        for (int i = 0; i < (BT * DIM / 4) / NTH; ++i) {   // 16 float4/thread
            int f  = tid + i * NTH;
            int r  = f >> 6;
            int c4 = f & 63;
            float4 x = src[f];
            __half2 h01 = __floats2half2_rn(x.x, x.y);
            __half2 h23 = __floats2half2_rn(x.z, x.w);
            *reinterpret_cast<__half2*>(sA + r * STR_AH + c4 * 4)     = h01;
            *reinterpret_cast<__half2*>(sA + r * STR_AH + c4 * 4 + 2) = h23;
        }
    }
    __syncthreads();    // only CTA-wide barrier in this kernel

    float* blkScr = g_qkv + (size_t)blockIdx.x * BLK_W;
    #pragma unroll 1
    for (int nc = 0; nc < 3; ++nc) {
        float acc[4][4][4] = {};
        gemm64(acc, g_wth + nc * DIM * DIM, svxS, laneOffB, sWw, swByte,
               lane, g, tig, wid * 32);
        // Write fragments transposed: scratch[sec][col][token]
        float* dst = blkScr + nc * SEC_W;
        #pragma unroll
        for (int mf = 0; mf < 4; ++mf) {
            #pragma unroll
            for (int j = 0; j < 4; ++j) {
                int col = wid * 32 + j * 8 + 2 * tig;
                int r0 = mf * 16 + g, r1 = r0 + 8;
                dst[col * BT + r0]       = acc[mf][j][0];
                dst[(col + 1) * BT + r0] = acc[mf][j][1];
                dst[col * BT + r1]       = acc[mf][j][2];
                dst[(col + 1) * BT + r1] = acc[mf][j][3];
            }
        }
    }
}

// ================= K2: heads-attention + output projection ==================
__global__ void __launch_bounds__(NTH, 2)
sa_attn_out_kernel(const float* __restrict__ bp, float* __restrict__ out) {
    extern __shared__ char smem[];
    __half*   sA  = reinterpret_cast<__half*>(smem);          // x tile (fp16)
    uint32_t* sWw = reinterpret_cast<uint32_t*>(smem + OFF_W);
    const uint32_t svxS   = (uint32_t)__cvta_generic_to_shared(smem);
    const uint32_t swByte = (uint32_t)__cvta_generic_to_shared(smem + OFF_W);

    const int tid  = threadIdx.x;
    const int wid  = tid >> 5;
    const int lane = tid & 31;
    const int g    = lane >> 2;
    const int tig  = lane & 3;
    const int t4   = lane >> 3;
    const int laneOffB = (((t4 & 1) * 8 + (lane & 7)) * STR_AH + (t4 >> 1) * 8) * 2;

    const float* blkScr = g_qkv + (size_t)blockIdx.x * BLK_W;

    // ---- Per-token heads-attention: warp = head (wid), 2 tokens per lane ---
    // Scratch is [col][token]; lane indexes token -> coalesced 128B loads.
    #pragma unroll 1
    for (int p = 0; p < BT / 32; ++p) {
        const int h = wid, t = p * 32 + lane;
        const float* qp = blkScr + (h * HD) * BT + t;
        const float* kp = blkScr + SEC_W + t;
        const float* vp = blkScr + 2 * SEC_W + t;

        float q[HD];
        #pragma unroll
        for (int d = 0; d < HD; ++d) q[d] = qp[d * BT];

        float a[NUM_H];
        float mx = -1e30f;
        #pragma unroll
        for (int gg = 0; gg < NUM_H; ++gg) {
            float s = 0.f;
            #pragma unroll
            for (int d = 0; d < HD; ++d) s += q[d] * kp[(gg * HD + d) * BT];
            s *= 0.17677669529663687f;   // 1/sqrt(32)
            a[gg] = s;
            mx = fmaxf(mx, s);
        }
        float sum = 0.f;
        #pragma unroll
        for (int gg = 0; gg < NUM_H; ++gg) { a[gg] = __expf(a[gg] - mx); sum += a[gg]; }
        float inv = 1.f / sum;
        #pragma unroll
        for (int gg = 0; gg < NUM_H; ++gg) a[gg] *= inv;

        // x[t, h*32 + d] -> fp16 A tile
        #pragma unroll
        for (int d2 = 0; d2 < HD / 2; ++d2) {
            float s0 = 0.f, s1 = 0.f;
            #pragma unroll
            for (int gg = 0; gg < NUM_H; ++gg) {
                s0 += a[gg] * vp[(gg * HD + 2 * d2) * BT];
                s1 += a[gg] * vp[(gg * HD + 2 * d2 + 1) * BT];
            }
            *reinterpret_cast<__half2*>(sA + t * STR_AH + h * HD + 2 * d2) =
                __floats2half2_rn(s0, s1);
        }
    }
    __syncthreads();    // x tile complete before GEMM reads cross-warp cols

    // ---- out = x @ Wp + bp (barrier-free GEMM)
    {
        float acc[4][4][4] = {};
        gemm64(acc, g_wth + 3 * DIM * DIM, svxS, laneOffB, sWw, swByte,
               lane, g, tig, wid * 32);

        float bias[4][2];
        #pragma unroll
        for (int j = 0; j < 4; ++j) {
            int n = wid * 32 + j * 8 + 2 * tig;
            bias[j][0] = bp[n];
            bias[j][1] = bp[n + 1];
        }
        float* outBlk = out + (size_t)blockIdx.x * BT * DIM;
        #pragma unroll
        for (int mf = 0; mf < 4; ++mf) {
            #pragma unroll
            for (int j = 0; j < 4; ++j) {
                int row = mf * 16 + g;
                int n = wid * 32 + j * 8 + 2 * tig;
                float2 lo = make_float2(acc[mf][j][0] + bias[j][0],
                                        acc[mf][j][1] + bias[j][1]);
                float2 hi = make_float2(acc[mf][j][2] + bias[j][0],
                                        acc[mf][j][3] + bias[j][1]);
                *reinterpret_cast<float2*>(outBlk + (size_t)row * DIM + n)       = lo;
                *reinterpret_cast<float2*>(outBlk + (size_t)(row + 8) * DIM + n) = hi;
            }
        }
    }
}

extern "C" void kernel_launch(void* const* d_in, const int* in_sizes, int n_in,
                              void* d_out, int out_size) {
    const float* v  = (const float*)d_in[0];
    const float* Wq = (const float*)d_in[1];
    const float* Wk = (const float*)d_in[2];
    const float* Wv = (const float*)d_in[3];
    const float* Wp = (const float*)d_in[4];
    const float* bp = (const float*)d_in[5];
    float* out = (float*)d_out;

    cudaFuncSetAttribute(sa_qkv_kernel,
                         cudaFuncAttributeMaxDynamicSharedMemorySize, SMEM_BYTES);
    cudaFuncSetAttribute(sa_attn_out_kernel,
                         cudaFuncAttributeMaxDynamicSharedMemorySize, SMEM_BYTES);

    int M = in_sizes[0] / DIM;          // 65536 tokens
    int grid = M / BT;                  // 1024 CTAs
    wt_transpose_kernel<<<4 * 64, NTH>>>(Wq, Wk, Wv, Wp);
    sa_qkv_kernel<<<grid, NTH, SMEM_BYTES>>>(v);
    sa_attn_out_kernel<<<grid, NTH, SMEM_BYTES>>>(bp, out);
}